// round 6
// baseline (speedup 1.0000x reference)
#include <cuda_runtime.h>
#include <cuda_bf16.h>
#include <cstdint>
#include <cstddef>

typedef unsigned long long ull;
typedef unsigned int u32;

#define BB 32
#define TT 1024
#define HH 512
#define GG 2048
#define LCTA 32                 // recurrence CTAs (bids 0..31)
#define XCTA 2048               // xproj CTAs (bids 32..2079)
#define UPC 16                  // h-units per recurrence CTA
#define PITCH_W 260             // words per h-image row (512 bf16 = 256 + 4 pad)
#define PLANE_B (32 * PITCH_W * 4)   // 33280 bytes per plane

// ---------------- device scratch (allocations are forbidden) ----------------
__device__ __align__(16) float g_xp[(size_t)TT * GG * BB];          // x_proj[t][g][b]
__device__ __align__(16) unsigned char g_h[2][2][PLANE_B];          // [phase][hi/lo][b][k] bf16
__device__ __align__(128) unsigned g_flags[LCTA * 8];               // h-step flags
__device__ __align__(128) unsigned g_tg[256];                       // xproj t-group counters

// ---------------- helpers ----------------
__device__ __forceinline__ ull ffma2(ull a, ull b, ull c) {
    ull d; asm("fma.rn.f32x2 %0, %1, %2, %3;" : "=l"(d) : "l"(a), "l"(b), "l"(c)); return d;
}
__device__ __forceinline__ ull fadd2(ull a, ull b) {
    ull d; asm("add.rn.f32x2 %0, %1, %2;" : "=l"(d) : "l"(a), "l"(b)); return d;
}
__device__ __forceinline__ ull pack2(float x, float y) {
    ull d; asm("mov.b64 %0, {%1, %2};" : "=l"(d) : "f"(x), "f"(y)); return d;
}
__device__ __forceinline__ float sigm(float x) { return __fdividef(1.0f, 1.0f + __expf(-x)); }
__device__ __forceinline__ float tanh_(float x) { return 1.0f - __fdividef(2.0f, __expf(2.0f * x) + 1.0f); }

__device__ __forceinline__ u32 smem_u32(const void* p) {
    u32 a; asm("{ .reg .u64 t; cvta.to.shared.u64 t, %1; cvt.u32.u64 %0, t; }" : "=r"(a) : "l"(p)); return a;
}
__device__ __forceinline__ void cp_async16(u32 dst, const void* src) {
    asm volatile("cp.async.cg.shared.global [%0], [%1], 16;" :: "r"(dst), "l"(src));
}
__device__ __forceinline__ u32 pack_bf2(float a, float b) {
    return (u32)__bfloat16_as_ushort(__float2bfloat16(a))
         | ((u32)__bfloat16_as_ushort(__float2bfloat16(b)) << 16);
}
__device__ __forceinline__ void mma16816(float& c0, float& c1, float& c2, float& c3,
                                         u32 a0, u32 a1, u32 a2, u32 a3, u32 b0, u32 b1) {
    asm volatile(
        "mma.sync.aligned.m16n8k16.row.col.f32.bf16.bf16.f32 "
        "{%0,%1,%2,%3}, {%4,%5,%6,%7}, {%8,%9}, {%0,%1,%2,%3};"
        : "+f"(c0), "+f"(c1), "+f"(c2), "+f"(c3)
        : "r"(a0), "r"(a1), "r"(a2), "r"(a3), "r"(b0), "r"(b1));
}

// ---------------- init: zero h planes, flags, t-group counters ----------------
__global__ void init_kernel() {
    int i = blockIdx.x * blockDim.x + threadIdx.x;
    uint4 z = {0, 0, 0, 0};
    const int n16 = (2 * 2 * PLANE_B) / 16;              // 8320
    if (i < n16) ((uint4*)g_h)[i] = z;
    if (i < LCTA * 8) g_flags[i] = 0u;
    if (i < 256) g_tg[i] = 0u;
}

// =========================================================================
// smem layout (shared between the two roles; max = lstm's 109,824 B)
// =========================================================================
#define SM_HI   0
#define SM_LO   PLANE_B                                  // 33280
#define SM_RED  (2 * PLANE_B)                            // 66560: red[4][64][40] f32
#define SM_OUTS (2 * PLANE_B + 4 * 64 * 40 * 4)          // 107520: out_s[32][18] f32
#define SM_TOT  (SM_OUTS + 32 * 18 * 4)                  // 109824

#define WPITCH 68
#define XPITCH 132
// xproj role uses the same buffer from offset 0: w_s 69632 B + x_s 33792 B = 103424 <= SM_TOT

// ---------------- xproj role: one 256g x 128n tile, K=512 ----------------
__device__ void xproj_role(int xbid, char* smc,
                           const float* __restrict__ src, const float* __restrict__ Wih,
                           const float* __restrict__ bih, const float* __restrict__ bhh)
{
    float* w_s = (float*)smc;
    float* x_s = (float*)smc + 256 * WPITCH;
    const int tid = threadIdx.x;
    const int tgroup = xbid >> 3;        // t-group-major: early t produced first
    const int gblock = xbid & 7;
    const int g0 = gblock * 256;
    const int t0 = tgroup * 4;
    const int ni = tid & 15;
    const int gi = tid >> 4;

    ull acc[32];
#pragma unroll
    for (int i = 0; i < 32; i++) acc[i] = 0ull;

    for (int kc = 0; kc < 8; kc++) {
        const int c0 = kc * 64;
#pragma unroll
        for (int i = 0; i < 8; i++) {
            int fq = tid + i * 512;
            int g = fq >> 4, cq = fq & 15;
            float4 wv = *(const float4*)(Wih + (size_t)(g0 + g) * HH + c0 + cq * 4);
            *(float4*)(w_s + g * WPITCH + cq * 4) = wv;
        }
#pragma unroll
        for (int i = 0; i < 4; i++) {
            int fq = tid + i * 512;
            int n = fq & 127, cq = fq >> 7;
            int b = n & 31, ti = n >> 5;
            float4 xv = *(const float4*)(src + ((size_t)b * TT + (t0 + ti)) * HH + c0 + cq * 4);
            x_s[(cq * 4 + 0) * XPITCH + n] = xv.x;
            x_s[(cq * 4 + 1) * XPITCH + n] = xv.y;
            x_s[(cq * 4 + 2) * XPITCH + n] = xv.z;
            x_s[(cq * 4 + 3) * XPITCH + n] = xv.w;
        }
        __syncthreads();

#pragma unroll 4
        for (int k = 0; k < 64; k++) {
            ulonglong2 xa = *(const ulonglong2*)(x_s + k * XPITCH + ni * 8);
            ulonglong2 xb = *(const ulonglong2*)(x_s + k * XPITCH + ni * 8 + 4);
            const float* wr = w_s + (gi * 8) * WPITCH + k;
#pragma unroll
            for (int i = 0; i < 8; i++) {
                float w = wr[i * WPITCH];
                ull w2 = pack2(w, w);
                acc[i * 4 + 0] = ffma2(xa.x, w2, acc[i * 4 + 0]);
                acc[i * 4 + 1] = ffma2(xa.y, w2, acc[i * 4 + 1]);
                acc[i * 4 + 2] = ffma2(xb.x, w2, acc[i * 4 + 2]);
                acc[i * 4 + 3] = ffma2(xb.y, w2, acc[i * 4 + 3]);
            }
        }
        __syncthreads();
    }

#pragma unroll
    for (int i = 0; i < 8; i++) {
        int g = g0 + gi * 8 + i;
        float bs = bih[g] + bhh[g];
        ull b2 = pack2(bs, bs);
#pragma unroll
        for (int p = 0; p < 4; p++) {
            int n = ni * 8 + 2 * p;
            int t = t0 + (n >> 5), b = n & 31;
            ull v = fadd2(acc[i * 4 + p], b2);
            *(ull*)(g_xp + ((size_t)t * GG + g) * BB + b) = v;
        }
    }

    // signal t-group completion (8 CTAs per t-group)
    __syncthreads();
    if (tid == 0) {
        __threadfence();
        atomicAdd(&g_tg[tgroup], 1u);
    }
}

// ---------------- lstm role: M=64 x N=32 x K=512, 16 warps ----------------
__device__ void lstm_role(int cta, char* smc,
                          const int* __restrict__ lengths, const float* __restrict__ Whh,
                          float* __restrict__ out)
{
    const u32 smem_base = smem_u32(smc);
    const u32* hi_w = (const u32*)(smc + SM_HI);
    const u32* lo_w = (const u32*)(smc + SM_LO);
    float* red_s = (float*)(smc + SM_RED);
    float* out_s = (float*)(smc + SM_OUTS);

    const int tid  = threadIdx.x;
    const int warp = tid >> 5;
    const int lane = tid & 31;
    const int g_   = lane >> 2;
    const int t_   = lane & 3;
    const int mg   = warp & 3;           // = gate index (16 rows each)
    const int kw   = warp >> 2;          // K chunk [kw*128, +128)

    // ---- prologue: W fragments (hi, lo) for 8 k-tiles
    u32 Ahi[8][4], Alo[8][4];
    {
        const float* p0 = Whh + (size_t)(mg * HH + cta * UPC + g_) * HH;
        const float* p1 = p0 + 8 * HH;
#pragma unroll
        for (int kt = 0; kt < 8; kt++) {
            int k0 = kw * 128 + kt * 16 + 2 * t_;
            float2 vv[4] = { *(const float2*)(p0 + k0), *(const float2*)(p1 + k0),
                             *(const float2*)(p0 + k0 + 8), *(const float2*)(p1 + k0 + 8) };
#pragma unroll
            for (int r = 0; r < 4; r++) {
                float hx = __bfloat162float(__float2bfloat16(vv[r].x));
                float hy = __bfloat162float(__float2bfloat16(vv[r].y));
                Ahi[kt][r] = pack_bf2(vv[r].x, vv[r].y);
                Alo[kt][r] = pack_bf2(vv[r].x - hx, vv[r].y - hy);
            }
        }
    }

    // updater mapping: unit ulocal = tid>>5? no: ub = tid & 31 (batch), ulocal = tid >> 5
    const int ub = tid & 31, ulocal = tid >> 5;   // 16 units x 32 batches = 512
    const int len = lengths[ub];
    float c_r = 0.0f, h_r = 0.0f;

    const int n16 = PLANE_B / 16;   // 2080

    for (int t = 0; t < TT; t++) {
        const int p = t & 1;

        // ---- wait: xproj t-group ready + all CTAs published step t-1
        if (tid == 32) {
            const unsigned* f = &g_tg[t >> 2];
            unsigned v;
            do {
                asm volatile("ld.acquire.gpu.u32 %0, [%1];" : "=r"(v) : "l"(f) : "memory");
            } while (v < 8u);
        }
        if (t > 0 && tid < LCTA) {
            const unsigned* f = &g_flags[tid * 8];
            unsigned v;
            do {
                asm volatile("ld.acquire.gpu.u32 %0, [%1];" : "=r"(v) : "l"(f) : "memory");
            } while (v < (unsigned)t);
        }
        __syncthreads();

        // ---- xg prefetch (consumed after MMA)
        float xg[4];
#pragma unroll
        for (int gt = 0; gt < 4; gt++)
            xg[gt] = g_xp[((size_t)t * GG + gt * HH + cta * UPC + ulocal) * BB + ub];

        // ---- stage hi plane, then lo plane
        const unsigned char* shi = g_h[p][0];
        const unsigned char* slo = g_h[p][1];
#pragma unroll
        for (int i = 0; i < 5; i++) {
            int idx = tid + i * 512;
            if (idx < n16) cp_async16(smem_base + SM_HI + idx * 16, shi + idx * 16);
        }
        asm volatile("cp.async.commit_group;" ::: "memory");
#pragma unroll
        for (int i = 0; i < 5; i++) {
            int idx = tid + i * 512;
            if (idx < n16) cp_async16(smem_base + SM_LO + idx * 16, slo + idx * 16);
        }
        asm volatile("cp.async.commit_group;" ::: "memory");

        asm volatile("cp.async.wait_group 1;" ::: "memory");
        __syncthreads();

        // ---- terms 1 & 3: (Whi + Wlo) * h_hi
        float C[4][4];
#pragma unroll
        for (int nt = 0; nt < 4; nt++)
#pragma unroll
            for (int r = 0; r < 4; r++) C[nt][r] = 0.0f;

#pragma unroll
        for (int kt = 0; kt < 8; kt++) {
            const int wbase = kw * 64 + kt * 8 + t_;
#pragma unroll
            for (int nt = 0; nt < 4; nt++) {
                const int n = nt * 8 + g_;
                u32 b0 = hi_w[n * PITCH_W + wbase];
                u32 b1 = hi_w[n * PITCH_W + wbase + 4];
                mma16816(C[nt][0], C[nt][1], C[nt][2], C[nt][3],
                         Ahi[kt][0], Ahi[kt][1], Ahi[kt][2], Ahi[kt][3], b0, b1);
                mma16816(C[nt][0], C[nt][1], C[nt][2], C[nt][3],
                         Alo[kt][0], Alo[kt][1], Alo[kt][2], Alo[kt][3], b0, b1);
            }
        }

        asm volatile("cp.async.wait_group 0;" ::: "memory");
        __syncthreads();

        // ---- term 2: Whi * h_lo
#pragma unroll
        for (int kt = 0; kt < 8; kt++) {
            const int wbase = kw * 64 + kt * 8 + t_;
#pragma unroll
            for (int nt = 0; nt < 4; nt++) {
                const int n = nt * 8 + g_;
                u32 b0 = lo_w[n * PITCH_W + wbase];
                u32 b1 = lo_w[n * PITCH_W + wbase + 4];
                mma16816(C[nt][0], C[nt][1], C[nt][2], C[nt][3],
                         Ahi[kt][0], Ahi[kt][1], Ahi[kt][2], Ahi[kt][3], b0, b1);
            }
        }

        // ---- write k-partials: red[kw][m][40], m = mg*16 + row
        {
            float* rw = red_s + (kw * 64 + mg * 16) * 40;
#pragma unroll
            for (int nt = 0; nt < 4; nt++) {
                int n = nt * 8 + 2 * t_;
                *(float2*)(rw + g_ * 40 + n)       = make_float2(C[nt][0], C[nt][1]);
                *(float2*)(rw + (g_ + 8) * 40 + n) = make_float2(C[nt][2], C[nt][3]);
            }
        }
        __syncthreads();

        // ---- updaters: reduce 4 k-partials, gates, state, publish
        float s[4];
#pragma unroll
        for (int gt = 0; gt < 4; gt++) {
            int m = gt * 16 + ulocal;
            float a0 = red_s[(0 * 64 + m) * 40 + ub] + red_s[(1 * 64 + m) * 40 + ub];
            float a1 = red_s[(2 * 64 + m) * 40 + ub] + red_s[(3 * 64 + m) * 40 + ub];
            s[gt] = a0 + a1;
        }
        float gi_ = sigm(xg[0] + s[0]);
        float gf  = sigm(xg[1] + s[1]);
        float gg  = tanh_(xg[2] + s[2]);
        float go  = sigm(xg[3] + s[3]);
        float cn = gf * c_r + gi_ * gg;
        float hn = go * tanh_(cn);
        bool valid = (t < len);
        if (valid) { c_r = cn; h_r = hn; }

        // publish h hi/lo bf16 into next-phase images
        {
            __nv_bfloat16 hh = __float2bfloat16(h_r);
            float rlo = h_r - __bfloat162float(hh);
            int kk = cta * UPC + ulocal;
            *(unsigned short*)(g_h[1 - p][0] + (size_t)ub * (PITCH_W * 4) + kk * 2)
                = __bfloat16_as_ushort(hh);
            *(unsigned short*)(g_h[1 - p][1] + (size_t)ub * (PITCH_W * 4) + kk * 2)
                = __bfloat16_as_ushort(__float2bfloat16(rlo));
        }
        out_s[ub * 18 + ulocal] = valid ? hn : 0.0f;
        __syncthreads();

        // release flag first, then coalesced output store
        if (tid == 0) {
            asm volatile("st.release.gpu.u32 [%0], %1;"
                         :: "l"(&g_flags[cta * 8]), "r"((unsigned)(t + 1)) : "memory");
        }
        {
            int b = tid >> 4, q = tid & 15;
            out[((size_t)t * BB + b) * HH + cta * UPC + q] = out_s[b * 18 + q];
        }
    }

    // final hT, cT
    {
        size_t base = (size_t)TT * BB * HH;
        out[base + (size_t)ub * HH + cta * UPC + ulocal] = h_r;
        out[base + (size_t)BB * HH + (size_t)ub * HH + cta * UPC + ulocal] = c_r;
    }
}

// =========================================================================
__global__ __launch_bounds__(512, 1) void fused_kernel(
    const float* __restrict__ src, const int* __restrict__ lengths,
    const float* __restrict__ Wih, const float* __restrict__ Whh,
    const float* __restrict__ bih, const float* __restrict__ bhh,
    float* __restrict__ out)
{
    extern __shared__ char smc[];
    const int bid = blockIdx.x;
    if (bid < LCTA) lstm_role(bid, smc, lengths, Whh, out);
    else            xproj_role(bid - LCTA, smc, src, Wih, bih, bhh);
}

// =========================================================================
extern "C" void kernel_launch(void* const* d_in, const int* in_sizes, int n_in,
                              void* d_out, int out_size) {
    const float* src  = (const float*)d_in[0];
    const int*   lens = (const int*)d_in[1];
    const float* Wih  = (const float*)d_in[2];
    const float* Whh  = (const float*)d_in[3];
    const float* bih  = (const float*)d_in[4];
    const float* bhh  = (const float*)d_in[5];
    float* out = (float*)d_out;

    cudaFuncSetAttribute(fused_kernel, cudaFuncAttributeMaxDynamicSharedMemorySize, SM_TOT);

    init_kernel<<<40, 256>>>();
    fused_kernel<<<LCTA + XCTA, 512, SM_TOT>>>(src, lens, Wih, Whh, bih, bhh, out);
}

// round 7
// speedup vs baseline: 1.3344x; 1.3344x over previous
#include <cuda_runtime.h>
#include <cuda_bf16.h>
#include <cstdint>
#include <cstddef>

typedef unsigned long long ull;
typedef unsigned int u32;

#define BB 32
#define TT 1024
#define HH 512
#define GG 2048
#define NCTA 128            // lstm CTAs
#define PKP 520             // packed h image pitch (words): 512 + 8

// ---------------- device scratch (allocations are forbidden) ----------------
__device__ __align__(16) float g_xp[(size_t)TT * GG * BB];   // x_proj[t][g][b]
__device__ __align__(16) u32 g_hpk[2][32 * PKP];             // packed (hi,lo) h images
__device__ __align__(128) unsigned g_flags[NCTA * 8];

// ---------------- helpers ----------------
__device__ __forceinline__ ull fadd2(ull a, ull b) {
    ull d; asm("add.rn.f32x2 %0, %1, %2;" : "=l"(d) : "l"(a), "l"(b)); return d;
}
__device__ __forceinline__ ull pack2(float x, float y) {
    ull d; asm("mov.b64 %0, {%1, %2};" : "=l"(d) : "f"(x), "f"(y)); return d;
}
__device__ __forceinline__ float sigm(float x) { return __fdividef(1.0f, 1.0f + __expf(-x)); }
__device__ __forceinline__ float tanh_(float x) { return 1.0f - __fdividef(2.0f, __expf(2.0f * x) + 1.0f); }

__device__ __forceinline__ u32 smem_u32(const void* p) {
    u32 a; asm("{ .reg .u64 t; cvta.to.shared.u64 t, %1; cvt.u32.u64 %0, t; }" : "=r"(a) : "l"(p)); return a;
}
__device__ __forceinline__ void cp_async16(u32 dst, const void* src) {
    asm volatile("cp.async.cg.shared.global [%0], [%1], 16;" :: "r"(dst), "l"(src));
}
__device__ __forceinline__ u32 pack_bf2(float a, float b) {
    return (u32)__bfloat16_as_ushort(__float2bfloat16(a))
         | ((u32)__bfloat16_as_ushort(__float2bfloat16(b)) << 16);
}
__device__ __forceinline__ void mma16816(float& c0, float& c1, float& c2, float& c3,
                                         u32 a0, u32 a1, u32 a2, u32 a3, u32 b0, u32 b1) {
    asm volatile(
        "mma.sync.aligned.m16n8k16.row.col.f32.bf16.bf16.f32 "
        "{%0,%1,%2,%3}, {%4,%5,%6,%7}, {%8,%9}, {%0,%1,%2,%3};"
        : "+f"(c0), "+f"(c1), "+f"(c2), "+f"(c3)
        : "r"(a0), "r"(a1), "r"(a2), "r"(a3), "r"(b0), "r"(b1));
}

// =========================================================================
// Kernel 1: HMMA x_proj. grid (16, 256): 128 g x 128 n per CTA, K chunks 64.
// 256 threads = 8 warps, warp tile 32m x 64n, 3-term bf16 split.
// CTA (0,0) also zeroes g_hpk + g_flags (consumed only by lstm, launched after).
// =========================================================================
#define APITCH 36            // 32 words (64 bf16) + 4 pad -> conflict-free frags
#define PLW (128 * APITCH)   // words per plane

__global__ __launch_bounds__(256, 1) void xproj_kernel(
    const float* __restrict__ src, const float* __restrict__ Wih,
    const float* __restrict__ bih, const float* __restrict__ bhh)
{
    extern __shared__ u32 smw[];
    u32* Ah = smw;
    u32* Al = smw + PLW;
    u32* Bh = smw + 2 * PLW;
    u32* Bl = smw + 3 * PLW;

    const int tid = threadIdx.x;
    if (blockIdx.x == 0 && blockIdx.y == 0) {
        uint4 z = {0, 0, 0, 0};
        const int n16 = (int)(sizeof(g_hpk) / 16);
        for (int i = tid; i < n16; i += 256) ((uint4*)g_hpk)[i] = z;
        for (int i = tid; i < NCTA * 8; i += 256) g_flags[i] = 0u;
    }

    const int g0 = blockIdx.x * 128;
    const int n0 = blockIdx.y * 128;
    const int warp = tid >> 5, lane = tid & 31;
    const int wm = warp & 3, wn = warp >> 2;     // warp grid 4m x 2n
    const int g_ = lane >> 2, t_ = lane & 3;

    float C[2][8][4];
#pragma unroll
    for (int mt = 0; mt < 2; mt++)
#pragma unroll
        for (int nt = 0; nt < 8; nt++)
#pragma unroll
            for (int r = 0; r < 4; r++) C[mt][nt][r] = 0.0f;

    for (int kc = 0; kc < 8; kc++) {
        const int c0 = kc * 64;
        // stage A = W_ih rows [g0, g0+128), cols [c0, c0+64), split hi/lo
#pragma unroll
        for (int i = 0; i < 8; i++) {
            int idx = tid + i * 256;              // 0..2047 float4s
            int row = idx >> 4, cq = idx & 15;
            float4 w = *(const float4*)(Wih + (size_t)(g0 + row) * HH + c0 + cq * 4);
            float hx = __bfloat162float(__float2bfloat16(w.x));
            float hy = __bfloat162float(__float2bfloat16(w.y));
            float hz = __bfloat162float(__float2bfloat16(w.z));
            float hw = __bfloat162float(__float2bfloat16(w.w));
            *(uint2*)(Ah + row * APITCH + cq * 2) =
                make_uint2(pack_bf2(w.x, w.y), pack_bf2(w.z, w.w));
            *(uint2*)(Al + row * APITCH + cq * 2) =
                make_uint2(pack_bf2(w.x - hx, w.y - hy), pack_bf2(w.z - hz, w.w - hw));
        }
        // stage B = src for n in [n0, n0+128): n -> (b, t)
#pragma unroll
        for (int i = 0; i < 8; i++) {
            int idx = tid + i * 256;
            int n = idx >> 4, cq = idx & 15;
            int N = n0 + n, b = N & 31, tt = N >> 5;
            float4 w = *(const float4*)(src + ((size_t)b * TT + tt) * HH + c0 + cq * 4);
            float hx = __bfloat162float(__float2bfloat16(w.x));
            float hy = __bfloat162float(__float2bfloat16(w.y));
            float hz = __bfloat162float(__float2bfloat16(w.z));
            float hw = __bfloat162float(__float2bfloat16(w.w));
            *(uint2*)(Bh + n * APITCH + cq * 2) =
                make_uint2(pack_bf2(w.x, w.y), pack_bf2(w.z, w.w));
            *(uint2*)(Bl + n * APITCH + cq * 2) =
                make_uint2(pack_bf2(w.x - hx, w.y - hy), pack_bf2(w.z - hz, w.w - hw));
        }
        __syncthreads();

#pragma unroll
        for (int kt = 0; kt < 4; kt++) {
            const int wbase = kt * 8 + t_;
            u32 ah[2][4], al[2][4];
#pragma unroll
            for (int mt = 0; mt < 2; mt++) {
                int ra = wm * 32 + mt * 16 + g_;
                ah[mt][0] = Ah[ra * APITCH + wbase];
                ah[mt][1] = Ah[(ra + 8) * APITCH + wbase];
                ah[mt][2] = Ah[ra * APITCH + wbase + 4];
                ah[mt][3] = Ah[(ra + 8) * APITCH + wbase + 4];
                al[mt][0] = Al[ra * APITCH + wbase];
                al[mt][1] = Al[(ra + 8) * APITCH + wbase];
                al[mt][2] = Al[ra * APITCH + wbase + 4];
                al[mt][3] = Al[(ra + 8) * APITCH + wbase + 4];
            }
#pragma unroll
            for (int nt = 0; nt < 8; nt++) {
                int nc = wn * 64 + nt * 8 + g_;
                u32 b0h = Bh[nc * APITCH + wbase];
                u32 b1h = Bh[nc * APITCH + wbase + 4];
                u32 b0l = Bl[nc * APITCH + wbase];
                u32 b1l = Bl[nc * APITCH + wbase + 4];
#pragma unroll
                for (int mt = 0; mt < 2; mt++) {
                    mma16816(C[mt][nt][0], C[mt][nt][1], C[mt][nt][2], C[mt][nt][3],
                             ah[mt][0], ah[mt][1], ah[mt][2], ah[mt][3], b0h, b1h);
                    mma16816(C[mt][nt][0], C[mt][nt][1], C[mt][nt][2], C[mt][nt][3],
                             al[mt][0], al[mt][1], al[mt][2], al[mt][3], b0h, b1h);
                    mma16816(C[mt][nt][0], C[mt][nt][1], C[mt][nt][2], C[mt][nt][3],
                             ah[mt][0], ah[mt][1], ah[mt][2], ah[mt][3], b0l, b1l);
                }
            }
        }
        __syncthreads();
    }

    // epilogue: + (b_ih + b_hh), store pairs to g_xp[t][g][b]
#pragma unroll
    for (int mt = 0; mt < 2; mt++) {
        int r0 = g0 + wm * 32 + mt * 16 + g_;
        int r1 = r0 + 8;
        float bs0 = bih[r0] + bhh[r0];
        float bs1 = bih[r1] + bhh[r1];
        ull bias0 = pack2(bs0, bs0), bias1 = pack2(bs1, bs1);
#pragma unroll
        for (int nt = 0; nt < 8; nt++) {
            int N = n0 + wn * 64 + nt * 8 + 2 * t_;
            int tt = N >> 5, b = N & 31;
            *(ull*)(g_xp + ((size_t)tt * GG + r0) * BB + b)
                = fadd2(pack2(C[mt][nt][0], C[mt][nt][1]), bias0);
            *(ull*)(g_xp + ((size_t)tt * GG + r1) * BB + b)
                = fadd2(pack2(C[mt][nt][2], C[mt][nt][3]), bias1);
        }
    }
}

// =========================================================================
// Kernel 2: HMMA recurrence, 128 CTAs x 256 thr, M=16 rows, packed h image.
// =========================================================================
#define SM_PK   0                               // u32[32][PKP] = 66,560 B
#define SM_RED  (32 * PKP * 4)                  // red[8][16][40] f32 = 20,480 B
#define SM_TOT_L (SM_RED + 8 * 16 * 40 * 4)     // 87,040 B

__global__ __launch_bounds__(256, 1) void lstm_kernel(
    const int* __restrict__ lengths, const float* __restrict__ Whh,
    float* __restrict__ out)
{
    extern __shared__ char smc[];
    const u32 smem_base = smem_u32(smc);
    const u32* pk = (const u32*)(smc + SM_PK);
    float* red_s = (float*)(smc + SM_RED);

    const int tid  = threadIdx.x;
    const int cta  = blockIdx.x;
    const int kw   = tid >> 5;           // warp = K chunk [kw*64, +64)
    const int lane = tid & 31;
    const int g_   = lane >> 2;
    const int t_   = lane & 3;

    // ---- prologue: W fragments (hi, lo), rows m = gate*4 + unit
    u32 Ahi[4][4], Alo[4][4];
    {
        const float* p0 = Whh + (size_t)((g_ >> 2) * HH + cta * 4 + (g_ & 3)) * HH;
        const float* p1 = p0 + (size_t)2 * HH * HH;   // rows +8 => gates 2,3
#pragma unroll
        for (int kt = 0; kt < 4; kt++) {
            int k0 = kw * 64 + kt * 16 + 2 * t_;
            float2 vv[4] = { *(const float2*)(p0 + k0), *(const float2*)(p1 + k0),
                             *(const float2*)(p0 + k0 + 8), *(const float2*)(p1 + k0 + 8) };
#pragma unroll
            for (int r = 0; r < 4; r++) {
                float hx = __bfloat162float(__float2bfloat16(vv[r].x));
                float hy = __bfloat162float(__float2bfloat16(vv[r].y));
                Ahi[kt][r] = pack_bf2(vv[r].x, vv[r].y);
                Alo[kt][r] = pack_bf2(vv[r].x - hx, vv[r].y - hy);
            }
        }
    }

    // updater mapping (tid < 128): ub = batch, uu = unit
    const int ub = tid >> 2, uu = tid & 3;
    int   len = 0;
    float c_r = 0.0f, h_r = 0.0f;
    if (tid < 128) len = lengths[ub];

    for (int t = 0; t < TT; t++) {
        const int p = t & 1;

        // xg prefetch (independent; in flight during poll)
        float xg0 = 0.f, xg1 = 0.f, xg2 = 0.f, xg3 = 0.f;
        if (tid < 128) {
            const float* xp = g_xp + ((size_t)t * GG + cta * 4 + uu) * BB + ub;
            xg0 = xp[0 * HH * BB];
            xg1 = xp[1 * HH * BB];
            xg2 = xp[2 * HH * BB];
            xg3 = xp[3 * HH * BB];
        }

        // grid barrier: all 128 CTAs published step t-1
        if (t > 0 && tid < NCTA) {
            const unsigned* f = &g_flags[tid * 8];
            unsigned v;
            do {
                asm volatile("ld.acquire.gpu.u32 %0, [%1];" : "=r"(v) : "l"(f) : "memory");
            } while (v < (unsigned)t);
        }
        __syncthreads();

        // stage packed h image (one plane, one wait)
        const u32* hsrc = g_hpk[p];
#pragma unroll
        for (int i = 0; i < 17; i++) {
            int idx = tid + i * 256;
            if (idx < (32 * PKP) / 4)
                cp_async16(smem_base + SM_PK + idx * 16, hsrc + idx * 4);
        }
        asm volatile("cp.async.commit_group;\ncp.async.wait_group 0;" ::: "memory");
        __syncthreads();

        // merged 3-term MMA: lo B-fragments derived via PRMT from the same words
        float C[4][4];
#pragma unroll
        for (int nt = 0; nt < 4; nt++)
#pragma unroll
            for (int r = 0; r < 4; r++) C[nt][r] = 0.0f;

#pragma unroll
        for (int kt = 0; kt < 4; kt++) {
            const int k0 = kw * 64 + kt * 16 + 2 * t_;
#pragma unroll
            for (int nt = 0; nt < 4; nt++) {
                const int n = nt * 8 + g_;
                uint2 wA = *(const uint2*)(pk + n * PKP + k0);
                uint2 wB = *(const uint2*)(pk + n * PKP + k0 + 8);
                u32 b0h = __byte_perm(wA.x, wA.y, 0x5410);
                u32 b1h = __byte_perm(wB.x, wB.y, 0x5410);
                u32 b0l = __byte_perm(wA.x, wA.y, 0x7632);
                u32 b1l = __byte_perm(wB.x, wB.y, 0x7632);
                mma16816(C[nt][0], C[nt][1], C[nt][2], C[nt][3],
                         Ahi[kt][0], Ahi[kt][1], Ahi[kt][2], Ahi[kt][3], b0h, b1h);
                mma16816(C[nt][0], C[nt][1], C[nt][2], C[nt][3],
                         Alo[kt][0], Alo[kt][1], Alo[kt][2], Alo[kt][3], b0h, b1h);
                mma16816(C[nt][0], C[nt][1], C[nt][2], C[nt][3],
                         Ahi[kt][0], Ahi[kt][1], Ahi[kt][2], Ahi[kt][3], b0l, b1l);
            }
        }

        // write k-partials: red[kw][m][40]
        {
            float* rw = red_s + kw * 16 * 40;
#pragma unroll
            for (int nt = 0; nt < 4; nt++) {
                int n = nt * 8 + 2 * t_;
                *(float2*)(rw + g_ * 40 + n)       = make_float2(C[nt][0], C[nt][1]);
                *(float2*)(rw + (g_ + 8) * 40 + n) = make_float2(C[nt][2], C[nt][3]);
            }
        }
        __syncthreads();

        // updaters: reduce 8 k-partials, gates, state, packed publish
        float out_val = 0.0f;
        if (tid < 128) {
            float s[4];
#pragma unroll
            for (int gt = 0; gt < 4; gt++) {
                int m = gt * 4 + uu;
                float a0 = 0.f, a1 = 0.f;
#pragma unroll
                for (int w = 0; w < 8; w += 2) {
                    a0 += red_s[(w * 16 + m) * 40 + ub];
                    a1 += red_s[((w + 1) * 16 + m) * 40 + ub];
                }
                s[gt] = a0 + a1;
            }
            float gi_ = sigm(xg0 + s[0]);
            float gf  = sigm(xg1 + s[1]);
            float gg  = tanh_(xg2 + s[2]);
            float go  = sigm(xg3 + s[3]);
            float cn = gf * c_r + gi_ * gg;
            float hn = go * tanh_(cn);
            bool valid = (t < len);
            if (valid) { c_r = cn; h_r = hn; }
            out_val = valid ? hn : 0.0f;

            // packed (hi, lo) publish: ONE 4B store
            __nv_bfloat16 hh = __float2bfloat16(h_r);
            float rlo = h_r - __bfloat162float(hh);
            u32 word = (u32)__bfloat16_as_ushort(hh)
                     | ((u32)__bfloat16_as_ushort(__float2bfloat16(rlo)) << 16);
            g_hpk[1 - p][ub * PKP + cta * 4 + uu] = word;
        }
        __syncthreads();

        // release flag first, then output store (off critical path)
        if (tid == 0) {
            asm volatile("st.release.gpu.u32 [%0], %1;"
                         :: "l"(&g_flags[cta * 8]), "r"((unsigned)(t + 1)) : "memory");
        }
        if (tid < 128) {
            out[((size_t)t * BB + ub) * HH + cta * 4 + uu] = out_val;
        }
    }

    // final hT, cT
    if (tid < 128) {
        size_t base = (size_t)TT * BB * HH;
        out[base + (size_t)ub * HH + cta * 4 + uu] = h_r;
        out[base + (size_t)BB * HH + (size_t)ub * HH + cta * 4 + uu] = c_r;
    }
}

// =========================================================================
extern "C" void kernel_launch(void* const* d_in, const int* in_sizes, int n_in,
                              void* d_out, int out_size) {
    const float* src  = (const float*)d_in[0];
    const int*   lens = (const int*)d_in[1];
    const float* Wih  = (const float*)d_in[2];
    const float* Whh  = (const float*)d_in[3];
    const float* bih  = (const float*)d_in[4];
    const float* bhh  = (const float*)d_in[5];
    float* out = (float*)d_out;

    const int smem_xproj = 4 * PLW * 4;          // 73,728 B
    cudaFuncSetAttribute(xproj_kernel, cudaFuncAttributeMaxDynamicSharedMemorySize, smem_xproj);
    cudaFuncSetAttribute(lstm_kernel,  cudaFuncAttributeMaxDynamicSharedMemorySize, SM_TOT_L);

    dim3 grid(16, 256);
    xproj_kernel<<<grid, 256, smem_xproj>>>(src, Wih, bih, bhh);
    lstm_kernel<<<NCTA, 256, SM_TOT_L>>>(lens, Whh, out);
}